// round 1
// baseline (speedup 1.0000x reference)
#include <cuda_runtime.h>
#include <math.h>

// ---------------- problem constants ----------------
#define BATCH     32768
#define NSPARSE   26
#define NDENSE    13
#define VOCAB     10000
#define EDIM      64
#define NHEAD     2
#define DHEAD     32
#define NLAYER    3
#define H1DIM     256
#define H2DIM     128
#define DNNIN     1677           // NDENSE + NSPARSE*EDIM
#define DNNIN_PAD 1680           // padded to multiple of 16 (pad cols are zero)
#define XCOLS     39
#define ATTFLAT   (NSPARSE*EDIM) // 1664
#define QKVR_C    256            // q|k|v|res concatenated
#define MROWS     (BATCH*NSPARSE)// 851968
#define STACKW    (ATTFLAT + H2DIM) // 1792

// ---------------- scratch (device globals; no runtime alloc allowed) -----
__device__ float g_att[(size_t)BATCH * ATTFLAT];       // current attention state (and final att_flat)
__device__ float g_qkvr[(size_t)MROWS * QKVR_C];       // per-layer q,k,v,res
__device__ float g_dnn_in[(size_t)BATCH * DNNIN_PAD];  // [dense(13) | emb(1664) | pad(3)=0]
__device__ float g_h1[(size_t)BATCH * H1DIM];          // DNN hidden 1

// ---------------- kernel 1: embedding gather + dnn input build -----------
__global__ void gather_kernel(const float* __restrict__ X,
                              const int*   __restrict__ sidx,
                              const float* __restrict__ emb) {
    long idx = (long)blockIdx.x * blockDim.x + threadIdx.x;
    long total = (long)BATCH * DNNIN_PAD;
    if (idx >= total) return;
    int b = (int)(idx / DNNIN_PAD);
    int c = (int)(idx % DNNIN_PAD);
    float v;
    if (c < NDENSE) {
        v = X[(long)b * XCOLS + NSPARSE + c];
    } else if (c < DNNIN) {
        int j = c - NDENSE;         // 0..1663
        int f = j >> 6;             // feature 0..25
        int e = j & 63;             // channel
        int row = sidx[(long)b * NSPARSE + f];
        v = emb[((long)f * VOCAB + row) * EDIM + e];
        g_att[(long)b * ATTFLAT + j] = v;   // initial attention state = embedding
    } else {
        v = 0.f;
    }
    g_dnn_in[idx] = v;
}

// ---------------- GEMM tiling params ----------------
#define GBM 128
#define GBN 128
#define GBK 16

// C (MROWS,256) = A(g_att: MROWS,64) @ [Wq|Wk|Wv|Wres] (64,256)
__global__ __launch_bounds__(256)
void proj_gemm(const float* __restrict__ Wq, const float* __restrict__ Wk,
               const float* __restrict__ Wv, const float* __restrict__ Wr) {
    __shared__ float As[GBK][GBM];
    __shared__ float Bs[GBK][GBN];
    int tid = threadIdx.x;
    long m0 = (long)blockIdx.x * GBM;
    int  n0 = blockIdx.y * GBN;
    int tm = (tid >> 4) << 3;
    int tn = (tid & 15) << 3;
    int arow = tid >> 1, akc = (tid & 1) << 3;
    int brow = tid >> 4, bcol = (tid & 15) << 3;
    const float* mats[4] = {Wq, Wk, Wv, Wr};
    const float* Wm = mats[(n0 + bcol) >> 6];
    int wcol = (n0 + bcol) & 63;

    float acc[8][8];
#pragma unroll
    for (int i = 0; i < 8; i++)
#pragma unroll
        for (int j = 0; j < 8; j++) acc[i][j] = 0.f;

    for (int k0 = 0; k0 < EDIM; k0 += GBK) {
        const float* ap = &g_att[(m0 + arow) * EDIM + k0 + akc];
        float4 a0 = *(const float4*)ap;
        float4 a1 = *(const float4*)(ap + 4);
        As[akc+0][arow] = a0.x; As[akc+1][arow] = a0.y;
        As[akc+2][arow] = a0.z; As[akc+3][arow] = a0.w;
        As[akc+4][arow] = a1.x; As[akc+5][arow] = a1.y;
        As[akc+6][arow] = a1.z; As[akc+7][arow] = a1.w;
        const float* wp = &Wm[(k0 + brow) * EDIM + wcol];
        *(float4*)&Bs[brow][bcol]     = *(const float4*)wp;
        *(float4*)&Bs[brow][bcol + 4] = *(const float4*)(wp + 4);
        __syncthreads();
#pragma unroll
        for (int kk = 0; kk < GBK; kk++) {
            float a[8], bv[8];
            *(float4*)&a[0]  = *(float4*)&As[kk][tm];
            *(float4*)&a[4]  = *(float4*)&As[kk][tm + 4];
            *(float4*)&bv[0] = *(float4*)&Bs[kk][tn];
            *(float4*)&bv[4] = *(float4*)&Bs[kk][tn + 4];
#pragma unroll
            for (int i = 0; i < 8; i++)
#pragma unroll
                for (int j = 0; j < 8; j++) acc[i][j] += a[i] * bv[j];
        }
        __syncthreads();
    }
#pragma unroll
    for (int i = 0; i < 8; i++) {
        float* cp = &g_qkvr[(m0 + tm + i) * QKVR_C + n0 + tn];
        *(float4*)cp       = make_float4(acc[i][0], acc[i][1], acc[i][2], acc[i][3]);
        *(float4*)(cp + 4) = make_float4(acc[i][4], acc[i][5], acc[i][6], acc[i][7]);
    }
}

// g_h1(B,256) = relu(g_dnn_in(B,1680) @ W1(1677,256) + b1)
__global__ __launch_bounds__(256)
void dnn_gemm(const float* __restrict__ W1, const float* __restrict__ b1) {
    __shared__ float As[GBK][GBM];
    __shared__ float Bs[GBK][GBN];
    int tid = threadIdx.x;
    long m0 = (long)blockIdx.x * GBM;
    int  n0 = blockIdx.y * GBN;
    int tm = (tid >> 4) << 3;
    int tn = (tid & 15) << 3;
    int arow = tid >> 1, akc = (tid & 1) << 3;
    int brow = tid >> 4, bcol = (tid & 15) << 3;

    float acc[8][8];
#pragma unroll
    for (int i = 0; i < 8; i++)
#pragma unroll
        for (int j = 0; j < 8; j++) acc[i][j] = 0.f;

    for (int k0 = 0; k0 < DNNIN_PAD; k0 += GBK) {
        const float* ap = &g_dnn_in[(m0 + arow) * (long)DNNIN_PAD + k0 + akc];
        float4 a0 = *(const float4*)ap;
        float4 a1 = *(const float4*)(ap + 4);
        As[akc+0][arow] = a0.x; As[akc+1][arow] = a0.y;
        As[akc+2][arow] = a0.z; As[akc+3][arow] = a0.w;
        As[akc+4][arow] = a1.x; As[akc+5][arow] = a1.y;
        As[akc+6][arow] = a1.z; As[akc+7][arow] = a1.w;
        int krow = k0 + brow;
        float4 w0, w1v;
        if (krow < DNNIN) {
            const float* wp = &W1[(long)krow * H1DIM + n0 + bcol];
            w0  = *(const float4*)wp;
            w1v = *(const float4*)(wp + 4);
        } else {
            w0 = make_float4(0.f, 0.f, 0.f, 0.f);
            w1v = w0;
        }
        *(float4*)&Bs[brow][bcol]     = w0;
        *(float4*)&Bs[brow][bcol + 4] = w1v;
        __syncthreads();
#pragma unroll
        for (int kk = 0; kk < GBK; kk++) {
            float a[8], bv[8];
            *(float4*)&a[0]  = *(float4*)&As[kk][tm];
            *(float4*)&a[4]  = *(float4*)&As[kk][tm + 4];
            *(float4*)&bv[0] = *(float4*)&Bs[kk][tn];
            *(float4*)&bv[4] = *(float4*)&Bs[kk][tn + 4];
#pragma unroll
            for (int i = 0; i < 8; i++)
#pragma unroll
                for (int j = 0; j < 8; j++) acc[i][j] += a[i] * bv[j];
        }
        __syncthreads();
    }
#pragma unroll
    for (int i = 0; i < 8; i++) {
#pragma unroll
        for (int j = 0; j < 8; j++) {
            float v = acc[i][j] + b1[n0 + tn + j];
            acc[i][j] = fmaxf(v, 0.f);
        }
        float* cp = &g_h1[(m0 + tm + i) * H1DIM + n0 + tn];
        *(float4*)cp       = make_float4(acc[i][0], acc[i][1], acc[i][2], acc[i][3]);
        *(float4*)(cp + 4) = make_float4(acc[i][4], acc[i][5], acc[i][6], acc[i][7]);
    }
}

// ---------------- kernel: scores/softmax/attn@v + residual + relu --------
// one block of 128 threads per sample
__global__ __launch_bounds__(128)
void attn_kernel() {
    __shared__ float s[NSPARSE * QKVR_C];              // q|k|v|res tile: 6656 floats
    __shared__ float sc[NHEAD * NSPARSE * NSPARSE];    // 1352 floats
    int b = blockIdx.x;
    int tid = threadIdx.x;
    const float4* src = (const float4*)&g_qkvr[(long)b * NSPARSE * QKVR_C];
    float4* s4 = (float4*)s;
    for (int i = tid; i < NSPARSE * QKVR_C / 4; i += 128) s4[i] = src[i];
    __syncthreads();
    // scores[h][i][j] = q_i . k_j  over head dims
    for (int idx = tid; idx < NHEAD * NSPARSE * NSPARSE; idx += 128) {
        int h = idx / (NSPARSE * NSPARSE);
        int r = idx % (NSPARSE * NSPARSE);
        int i = r / NSPARSE, j = r % NSPARSE;
        const float* qp = &s[i * QKVR_C + h * DHEAD];
        const float* kp = &s[j * QKVR_C + EDIM + h * DHEAD];
        float acc = 0.f;
#pragma unroll
        for (int d = 0; d < DHEAD; d++) acc += qp[d] * kp[d];
        sc[idx] = acc;
    }
    __syncthreads();
    // stable softmax over j (52 rows)
    if (tid < NHEAD * NSPARSE) {
        float* row = &sc[tid * NSPARSE];  // (h*26+i)*26 == h*676+i*26
        float m = row[0];
        for (int j = 1; j < NSPARSE; j++) m = fmaxf(m, row[j]);
        float ssum = 0.f;
        for (int j = 0; j < NSPARSE; j++) { float e = expf(row[j] - m); row[j] = e; ssum += e; }
        float inv = 1.f / ssum;
        for (int j = 0; j < NSPARSE; j++) row[j] *= inv;
    }
    __syncthreads();
    // out = attn @ v + res, relu, write back into g_att
    for (int idx = tid; idx < ATTFLAT; idx += 128) {
        int f = idx >> 6, o = idx & 63, h = o >> 5;
        float acc = s[f * QKVR_C + 192 + o];           // residual (att @ Wres)
        const float* scr = &sc[(h * NSPARSE + f) * NSPARSE];
#pragma unroll
        for (int j = 0; j < NSPARSE; j++) acc += scr[j] * s[j * QKVR_C + 128 + o];
        g_att[(long)b * ATTFLAT + idx] = fmaxf(acc, 0.f);
    }
}

// ---------------- kernel: dnn layer2 + head + sigmoid --------------------
#define FIN_SPB 64
#define FIN_SMEM ((H1DIM*H2DIM + STACKW + H1DIM + 256) * sizeof(float))
__global__ __launch_bounds__(256)
void final_kernel(const float* __restrict__ X,
                  const float* __restrict__ W2, const float* __restrict__ b2,
                  const float* __restrict__ outW,
                  const float* __restrict__ linW, const float* __restrict__ linb,
                  float* __restrict__ out) {
    extern __shared__ float sm[];
    float* sW2   = sm;                       // 32768
    float* soutW = sW2 + H1DIM * H2DIM;      // 1792
    float* sh1   = soutW + STACKW;           // 256
    float* red   = sh1 + H1DIM;              // 256
    int tid = threadIdx.x;
    for (int i = tid; i < H1DIM * H2DIM; i += 256) sW2[i] = W2[i];
    for (int i = tid; i < STACKW; i += 256)        soutW[i] = outW[i];
    __syncthreads();
    int b0 = blockIdx.x * FIN_SPB;
    for (int sIdx = 0; sIdx < FIN_SPB; sIdx++) {
        int b = b0 + sIdx;
        sh1[tid] = g_h1[(long)b * H1DIM + tid];
        __syncthreads();
        float p;
        if (tid < H2DIM) {
            // h2[tid] = relu(h1 . W2[:,tid] + b2[tid]); contribute h2*outW
            float acc = b2[tid];
#pragma unroll 8
            for (int k = 0; k < H1DIM; k++) acc += sh1[k] * sW2[k * H2DIM + tid];
            acc = fmaxf(acc, 0.f);
            p = acc * soutW[ATTFLAT + tid];
        } else {
            // att_flat . outW[:1664]
            float acc = 0.f;
            const float* ap = &g_att[(long)b * ATTFLAT];
            for (int i = tid - H2DIM; i < ATTFLAT; i += 128) acc += ap[i] * soutW[i];
            p = acc;
        }
        red[tid] = p;
        __syncthreads();
        for (int st = 128; st > 0; st >>= 1) {
            if (tid < st) red[tid] += red[tid + st];
            __syncthreads();
        }
        if (tid == 0) {
            float lin = linb[0];
            const float* xp = &X[(long)b * XCOLS];
            for (int j = 0; j < XCOLS; j++) lin += xp[j] * linW[j];
            lin = fmaxf(lin, 0.f);
            float logit = lin + red[0];
            out[b] = 1.f / (1.f + expf(-logit));
        }
        __syncthreads();
    }
}

// ---------------- launcher ----------------
extern "C" void kernel_launch(void* const* d_in, const int* in_sizes, int n_in,
                              void* d_out, int out_size) {
    (void)in_sizes; (void)n_in; (void)out_size;
    const float* X    = (const float*)d_in[0];
    const int*   sidx = (const int*)  d_in[1];
    const float* emb  = (const float*)d_in[2];
    const float* Wq   = (const float*)d_in[3];
    const float* Wk   = (const float*)d_in[4];
    const float* Wv   = (const float*)d_in[5];
    const float* Wr   = (const float*)d_in[6];
    const float* W1   = (const float*)d_in[7];
    const float* b1   = (const float*)d_in[8];
    const float* W2   = (const float*)d_in[9];
    const float* b2   = (const float*)d_in[10];
    const float* outW = (const float*)d_in[11];
    const float* linW = (const float*)d_in[12];
    const float* linb = (const float*)d_in[13];
    float* out = (float*)d_out;

    // 1) gather embeddings, build dnn input, init attention state
    {
        long total = (long)BATCH * DNNIN_PAD;
        int blocks = (int)((total + 255) / 256);
        gather_kernel<<<blocks, 256>>>(X, sidx, emb);
    }
    // 2) three interacting layers
    for (int l = 0; l < NLAYER; l++) {
        proj_gemm<<<dim3(MROWS / GBM, QKVR_C / GBN), 256>>>(
            Wq + (long)l * EDIM * EDIM, Wk + (long)l * EDIM * EDIM,
            Wv + (long)l * EDIM * EDIM, Wr + (long)l * EDIM * EDIM);
        attn_kernel<<<BATCH, 128>>>();
    }
    // 3) DNN layer 1
    dnn_gemm<<<dim3(BATCH / GBM, H1DIM / GBN), 256>>>(W1, b1);
    // 4) DNN layer 2 + output head
    cudaFuncSetAttribute((const void*)final_kernel,
                         cudaFuncAttributeMaxDynamicSharedMemorySize, (int)FIN_SMEM);
    final_kernel<<<BATCH / FIN_SPB, 256, FIN_SMEM>>>(X, W2, b2, outW, linW, linb, out);
}

// round 3
// speedup vs baseline: 1.5074x; 1.5074x over previous
#include <cuda_runtime.h>
#include <math.h>

// ---------------- problem constants ----------------
#define BATCH     32768
#define NSPARSE   26
#define NDENSE    13
#define VOCAB     10000
#define EDIM      64
#define NHEAD     2
#define DHEAD     32
#define NLAYER    3
#define H1DIM     256
#define H2DIM     128
#define DNNIN     1677           // NDENSE + NSPARSE*EDIM
#define DNNIN_PAD 1680           // padded to multiple of 16 (pad cols are zero)
#define XCOLS     39
#define ATTFLAT   (NSPARSE*EDIM) // 1664
#define QKVR_C    256            // q|k|v|res concatenated
#define MROWS     (BATCH*NSPARSE)// 851968
#define STACKW    (ATTFLAT + H2DIM) // 1792

// ---------------- scratch (device globals) ----------------
__device__ float g_att[(size_t)BATCH * ATTFLAT];
__device__ float g_qkvr[(size_t)MROWS * QKVR_C];
__device__ float g_dnn_in[(size_t)BATCH * DNNIN_PAD];
__device__ float g_h1[(size_t)BATCH * H1DIM];
__device__ float g_h2[(size_t)BATCH * H2DIM];

// ---------------- packed f32x2 helpers ----------------
__device__ __forceinline__ unsigned long long dupf(float x) {
    unsigned long long r;
    asm("mov.b64 %0, {%1, %1};" : "=l"(r) : "f"(x));
    return r;
}
__device__ __forceinline__ void ffma2(unsigned long long& acc,
                                      unsigned long long a,
                                      unsigned long long b) {
    asm("fma.rn.f32x2 %0, %1, %2, %0;" : "+l"(acc) : "l"(a), "l"(b));
}
__device__ __forceinline__ float2 unpk(unsigned long long v) {
    float2 f;
    asm("mov.b64 {%0, %1}, %2;" : "=f"(f.x), "=f"(f.y) : "l"(v));
    return f;
}

// ---------------- kernel 1: embedding gather + dnn input build -----------
__global__ void gather_kernel(const float* __restrict__ X,
                              const int*   __restrict__ sidx,
                              const float* __restrict__ emb) {
    long idx = (long)blockIdx.x * blockDim.x + threadIdx.x;
    long total = (long)BATCH * DNNIN_PAD;
    if (idx >= total) return;
    int b = (int)(idx / DNNIN_PAD);
    int c = (int)(idx % DNNIN_PAD);
    float v;
    if (c < NDENSE) {
        v = X[(long)b * XCOLS + NSPARSE + c];
    } else if (c < DNNIN) {
        int j = c - NDENSE;
        int f = j >> 6;
        int e = j & 63;
        int row = sidx[(long)b * NSPARSE + f];
        v = emb[((long)f * VOCAB + row) * EDIM + e];
        g_att[(long)b * ATTFLAT + j] = v;
    } else {
        v = 0.f;
    }
    g_dnn_in[idx] = v;
}

// ---------------- GEMM tiling params ----------------
#define GBM 128
#define GBN 128
#define GBK 16

// C (MROWS,256) = A(g_att: MROWS,64) @ [Wq|Wk|Wv|Wres] (64,256), f32x2 packed
__global__ __launch_bounds__(256)
void proj_gemm(const float* __restrict__ Wq, const float* __restrict__ Wk,
               const float* __restrict__ Wv, const float* __restrict__ Wr) {
    __shared__ __align__(16) unsigned long long As2[GBK][GBM]; // A duplicated pairs
    __shared__ __align__(16) float Bs[GBK][GBN];
    int tid = threadIdx.x;
    long m0 = (long)blockIdx.x * GBM;
    int  n0 = blockIdx.y * GBN;
    int tm = (tid >> 4) << 3;
    int tn = (tid & 15) << 3;
    int arow = tid >> 1, akc = (tid & 1) << 3;
    int brow = tid >> 4, bcol = (tid & 15) << 3;
    const float* mats[4] = {Wq, Wk, Wv, Wr};
    const float* Wm = mats[(n0 + bcol) >> 6];
    int wcol = (n0 + bcol) & 63;

    unsigned long long acc[8][4];
#pragma unroll
    for (int i = 0; i < 8; i++)
#pragma unroll
        for (int j = 0; j < 4; j++) acc[i][j] = 0ull;

    for (int k0 = 0; k0 < EDIM; k0 += GBK) {
        const float* ap = &g_att[(m0 + arow) * EDIM + k0 + akc];
        float4 a0 = *(const float4*)ap;
        float4 a1 = *(const float4*)(ap + 4);
        As2[akc+0][arow] = dupf(a0.x); As2[akc+1][arow] = dupf(a0.y);
        As2[akc+2][arow] = dupf(a0.z); As2[akc+3][arow] = dupf(a0.w);
        As2[akc+4][arow] = dupf(a1.x); As2[akc+5][arow] = dupf(a1.y);
        As2[akc+6][arow] = dupf(a1.z); As2[akc+7][arow] = dupf(a1.w);
        const float* wp = &Wm[(k0 + brow) * EDIM + wcol];
        *(float4*)&Bs[brow][bcol]     = *(const float4*)wp;
        *(float4*)&Bs[brow][bcol + 4] = *(const float4*)(wp + 4);
        __syncthreads();
#pragma unroll
        for (int kk = 0; kk < GBK; kk++) {
            unsigned long long av[8], bv[4];
            ulonglong2 t0 = *(const ulonglong2*)&As2[kk][tm];
            ulonglong2 t1 = *(const ulonglong2*)&As2[kk][tm + 2];
            ulonglong2 t2 = *(const ulonglong2*)&As2[kk][tm + 4];
            ulonglong2 t3 = *(const ulonglong2*)&As2[kk][tm + 6];
            av[0]=t0.x; av[1]=t0.y; av[2]=t1.x; av[3]=t1.y;
            av[4]=t2.x; av[5]=t2.y; av[6]=t3.x; av[7]=t3.y;
            ulonglong2 u0 = *(const ulonglong2*)&Bs[kk][tn];
            ulonglong2 u1 = *(const ulonglong2*)&Bs[kk][tn + 4];
            bv[0]=u0.x; bv[1]=u0.y; bv[2]=u1.x; bv[3]=u1.y;
#pragma unroll
            for (int i = 0; i < 8; i++)
#pragma unroll
                for (int j = 0; j < 4; j++) ffma2(acc[i][j], av[i], bv[j]);
        }
        __syncthreads();
    }
#pragma unroll
    for (int i = 0; i < 8; i++) {
        float2 c0 = unpk(acc[i][0]), c1 = unpk(acc[i][1]);
        float2 c2 = unpk(acc[i][2]), c3 = unpk(acc[i][3]);
        float* cp = &g_qkvr[(m0 + tm + i) * QKVR_C + n0 + tn];
        *(float4*)cp       = make_float4(c0.x, c0.y, c1.x, c1.y);
        *(float4*)(cp + 4) = make_float4(c2.x, c2.y, c3.x, c3.y);
    }
}

// g_h1(B,256) = relu(g_dnn_in(B,1680) @ W1(1677,256) + b1), f32x2 packed
__global__ __launch_bounds__(256)
void dnn_gemm(const float* __restrict__ W1, const float* __restrict__ b1) {
    __shared__ __align__(16) unsigned long long As2[GBK][GBM];
    __shared__ __align__(16) float Bs[GBK][GBN];
    int tid = threadIdx.x;
    long m0 = (long)blockIdx.x * GBM;
    int  n0 = blockIdx.y * GBN;
    int tm = (tid >> 4) << 3;
    int tn = (tid & 15) << 3;
    int arow = tid >> 1, akc = (tid & 1) << 3;
    int brow = tid >> 4, bcol = (tid & 15) << 3;

    unsigned long long acc[8][4];
#pragma unroll
    for (int i = 0; i < 8; i++)
#pragma unroll
        for (int j = 0; j < 4; j++) acc[i][j] = 0ull;

    for (int k0 = 0; k0 < DNNIN_PAD; k0 += GBK) {
        const float* ap = &g_dnn_in[(m0 + arow) * (long)DNNIN_PAD + k0 + akc];
        float4 a0 = *(const float4*)ap;
        float4 a1 = *(const float4*)(ap + 4);
        As2[akc+0][arow] = dupf(a0.x); As2[akc+1][arow] = dupf(a0.y);
        As2[akc+2][arow] = dupf(a0.z); As2[akc+3][arow] = dupf(a0.w);
        As2[akc+4][arow] = dupf(a1.x); As2[akc+5][arow] = dupf(a1.y);
        As2[akc+6][arow] = dupf(a1.z); As2[akc+7][arow] = dupf(a1.w);
        int krow = k0 + brow;
        float4 w0, w1v;
        if (krow < DNNIN) {
            const float* wp = &W1[(long)krow * H1DIM + n0 + bcol];
            w0  = *(const float4*)wp;
            w1v = *(const float4*)(wp + 4);
        } else {
            w0 = make_float4(0.f, 0.f, 0.f, 0.f);
            w1v = w0;
        }
        *(float4*)&Bs[brow][bcol]     = w0;
        *(float4*)&Bs[brow][bcol + 4] = w1v;
        __syncthreads();
#pragma unroll
        for (int kk = 0; kk < GBK; kk++) {
            unsigned long long av[8], bv[4];
            ulonglong2 t0 = *(const ulonglong2*)&As2[kk][tm];
            ulonglong2 t1 = *(const ulonglong2*)&As2[kk][tm + 2];
            ulonglong2 t2 = *(const ulonglong2*)&As2[kk][tm + 4];
            ulonglong2 t3 = *(const ulonglong2*)&As2[kk][tm + 6];
            av[0]=t0.x; av[1]=t0.y; av[2]=t1.x; av[3]=t1.y;
            av[4]=t2.x; av[5]=t2.y; av[6]=t3.x; av[7]=t3.y;
            ulonglong2 u0 = *(const ulonglong2*)&Bs[kk][tn];
            ulonglong2 u1 = *(const ulonglong2*)&Bs[kk][tn + 4];
            bv[0]=u0.x; bv[1]=u0.y; bv[2]=u1.x; bv[3]=u1.y;
#pragma unroll
            for (int i = 0; i < 8; i++)
#pragma unroll
                for (int j = 0; j < 4; j++) ffma2(acc[i][j], av[i], bv[j]);
        }
        __syncthreads();
    }
#pragma unroll
    for (int i = 0; i < 8; i++) {
        float2 c[4];
        c[0] = unpk(acc[i][0]); c[1] = unpk(acc[i][1]);
        c[2] = unpk(acc[i][2]); c[3] = unpk(acc[i][3]);
        float o[8];
#pragma unroll
        for (int j = 0; j < 4; j++) {
            o[2*j]   = fmaxf(c[j].x + b1[n0 + tn + 2*j], 0.f);
            o[2*j+1] = fmaxf(c[j].y + b1[n0 + tn + 2*j+1], 0.f);
        }
        float* cp = &g_h1[(m0 + tm + i) * H1DIM + n0 + tn];
        *(float4*)cp       = make_float4(o[0], o[1], o[2], o[3]);
        *(float4*)(cp + 4) = make_float4(o[4], o[5], o[6], o[7]);
    }
}

// g_h2(B,128) = relu(g_h1(B,256) @ W2(256,128) + b2), f32x2 packed
__global__ __launch_bounds__(256)
void h2_gemm(const float* __restrict__ W2, const float* __restrict__ b2) {
    __shared__ __align__(16) unsigned long long As2[GBK][GBM];
    __shared__ __align__(16) float Bs[GBK][H2DIM];
    int tid = threadIdx.x;
    long m0 = (long)blockIdx.x * GBM;
    int tm = (tid >> 4) << 3;
    int tn = (tid & 15) << 3;
    int arow = tid >> 1, akc = (tid & 1) << 3;
    int brow = tid >> 4, bcol = (tid & 15) << 3;

    unsigned long long acc[8][4];
#pragma unroll
    for (int i = 0; i < 8; i++)
#pragma unroll
        for (int j = 0; j < 4; j++) acc[i][j] = 0ull;

    for (int k0 = 0; k0 < H1DIM; k0 += GBK) {
        const float* ap = &g_h1[(m0 + arow) * H1DIM + k0 + akc];
        float4 a0 = *(const float4*)ap;
        float4 a1 = *(const float4*)(ap + 4);
        As2[akc+0][arow] = dupf(a0.x); As2[akc+1][arow] = dupf(a0.y);
        As2[akc+2][arow] = dupf(a0.z); As2[akc+3][arow] = dupf(a0.w);
        As2[akc+4][arow] = dupf(a1.x); As2[akc+5][arow] = dupf(a1.y);
        As2[akc+6][arow] = dupf(a1.z); As2[akc+7][arow] = dupf(a1.w);
        const float* wp = &W2[(long)(k0 + brow) * H2DIM + bcol];
        *(float4*)&Bs[brow][bcol]     = *(const float4*)wp;
        *(float4*)&Bs[brow][bcol + 4] = *(const float4*)(wp + 4);
        __syncthreads();
#pragma unroll
        for (int kk = 0; kk < GBK; kk++) {
            unsigned long long av[8], bv[4];
            ulonglong2 t0 = *(const ulonglong2*)&As2[kk][tm];
            ulonglong2 t1 = *(const ulonglong2*)&As2[kk][tm + 2];
            ulonglong2 t2 = *(const ulonglong2*)&As2[kk][tm + 4];
            ulonglong2 t3 = *(const ulonglong2*)&As2[kk][tm + 6];
            av[0]=t0.x; av[1]=t0.y; av[2]=t1.x; av[3]=t1.y;
            av[4]=t2.x; av[5]=t2.y; av[6]=t3.x; av[7]=t3.y;
            ulonglong2 u0 = *(const ulonglong2*)&Bs[kk][tn];
            ulonglong2 u1 = *(const ulonglong2*)&Bs[kk][tn + 4];
            bv[0]=u0.x; bv[1]=u0.y; bv[2]=u1.x; bv[3]=u1.y;
#pragma unroll
            for (int i = 0; i < 8; i++)
#pragma unroll
                for (int j = 0; j < 4; j++) ffma2(acc[i][j], av[i], bv[j]);
        }
        __syncthreads();
    }
#pragma unroll
    for (int i = 0; i < 8; i++) {
        float2 c[4];
        c[0] = unpk(acc[i][0]); c[1] = unpk(acc[i][1]);
        c[2] = unpk(acc[i][2]); c[3] = unpk(acc[i][3]);
        float o[8];
#pragma unroll
        for (int j = 0; j < 4; j++) {
            o[2*j]   = fmaxf(c[j].x + b2[tn + 2*j], 0.f);
            o[2*j+1] = fmaxf(c[j].y + b2[tn + 2*j+1], 0.f);
        }
        float* cp = &g_h2[(m0 + tm + i) * H2DIM + tn];
        *(float4*)cp       = make_float4(o[0], o[1], o[2], o[3]);
        *(float4*)(cp + 4) = make_float4(o[4], o[5], o[6], o[7]);
    }
}

// ---------------- attention: warp per (sample, head) ----------------
#define AT_SAMPLES 2
#define AT_STRIDE  260   // qkvr row stride in floats (bank-conflict-free pads)
__global__ __launch_bounds__(128)
void attn_kernel() {
    __shared__ __align__(16) float s[AT_SAMPLES * NSPARSE * AT_STRIDE]; // 54 KB
    __shared__ float p_s[AT_SAMPLES * NHEAD * NSPARSE * 32];            // 13 KB
    int tid = threadIdx.x;
    int warp = tid >> 5, lane = tid & 31;
    int ls = warp >> 1;       // local sample
    int h  = warp & 1;        // head
    long b0 = (long)blockIdx.x * AT_SAMPLES;

    // cooperative coalesced load of 2 samples' qkvr into padded smem
    const float4* src = (const float4*)&g_qkvr[(size_t)b0 * NSPARSE * QKVR_C];
    for (int i = tid; i < AT_SAMPLES * NSPARSE * (QKVR_C / 4); i += 128) {
        int r = i >> 6;     // row (sample*26 + feat)
        int c = i & 63;     // float4 within row
        *(float4*)&s[r * AT_STRIDE + 4 * c] = src[i];
    }
    __syncthreads();

    float* st = &s[ls * NSPARSE * AT_STRIDE];

    // k into registers: lane j holds k_j[0..31]
    float kreg[32];
    if (lane < NSPARSE) {
        const float* kp = &st[lane * AT_STRIDE + EDIM + h * DHEAD];
#pragma unroll
        for (int d = 0; d < 32; d += 4) {
            float4 t = *(const float4*)&kp[d];
            kreg[d] = t.x; kreg[d+1] = t.y; kreg[d+2] = t.z; kreg[d+3] = t.w;
        }
    } else {
#pragma unroll
        for (int d = 0; d < 32; d++) kreg[d] = 0.f;
    }

    // scores: sc[i] on lane j = q_i . k_j
    float sc[NSPARSE];
#pragma unroll
    for (int i = 0; i < NSPARSE; i++) {
        const float* qp = &st[i * AT_STRIDE + h * DHEAD];
        float acc = 0.f;
#pragma unroll
        for (int d = 0; d < 32; d += 4) {
            float4 q4 = *(const float4*)&qp[d];   // broadcast
            acc += q4.x * kreg[d] + q4.y * kreg[d+1]
                 + q4.z * kreg[d+2] + q4.w * kreg[d+3];
        }
        sc[i] = (lane < NSPARSE) ? acc : -INFINITY;
    }

    // softmax across lanes (j) per row i, write p to smem
    float* pp = &p_s[(ls * NHEAD + h) * NSPARSE * 32];
#pragma unroll
    for (int i = 0; i < NSPARSE; i++) {
        float m = sc[i];
#pragma unroll
        for (int o = 16; o > 0; o >>= 1) m = fmaxf(m, __shfl_xor_sync(0xffffffffu, m, o));
        float e = expf(sc[i] - m);          // inactive lanes: exp(-inf)=0
        float ssum = e;
#pragma unroll
        for (int o = 16; o > 0; o >>= 1) ssum += __shfl_xor_sync(0xffffffffu, ssum, o);
        pp[i * 32 + lane] = e / ssum;
    }
    __syncwarp();

    // v into registers: lane=d holds v_j[d] for all j
    float vreg[NSPARSE];
#pragma unroll
    for (int j = 0; j < NSPARSE; j++)
        vreg[j] = st[j * AT_STRIDE + 2 * EDIM + h * DHEAD + lane];

    // out[i][lane] = res + sum_j p[i][j] * v[j][lane], relu, store
    float* dst = &g_att[(size_t)(b0 + ls) * ATTFLAT + h * DHEAD + lane];
#pragma unroll
    for (int i = 0; i < NSPARSE; i++) {
        float acc = st[i * AT_STRIDE + 3 * EDIM + h * DHEAD + lane];  // residual
        const float* pr = &pp[i * 32];
#pragma unroll
        for (int j = 0; j < 24; j += 4) {
            float4 p4 = *(const float4*)&pr[j];   // broadcast
            acc += p4.x * vreg[j] + p4.y * vreg[j+1]
                 + p4.z * vreg[j+2] + p4.w * vreg[j+3];
        }
        acc += pr[24] * vreg[24] + pr[25] * vreg[25];
        dst[i * EDIM] = fmaxf(acc, 0.f);
    }
}

// ---------------- head: per-sample dots + sigmoid ----------------
__global__ __launch_bounds__(256)
void head_kernel(const float* __restrict__ X,
                 const float* __restrict__ outW,
                 const float* __restrict__ linW, const float* __restrict__ linb,
                 float* __restrict__ out) {
    __shared__ __align__(16) float soW[STACKW];
    int tid = threadIdx.x;
    for (int i = tid; i < STACKW; i += 256) soW[i] = outW[i];
    __syncthreads();
    int warp = tid >> 5, lane = tid & 31;
    int s = blockIdx.x * 8 + warp;
    const float4* ap  = (const float4*)&g_att[(size_t)s * ATTFLAT];
    const float4* ow4 = (const float4*)soW;
    float acc = 0.f;
#pragma unroll
    for (int t = 0; t < 13; t++) {
        int i = t * 32 + lane;
        float4 a = ap[i]; float4 w = ow4[i];
        acc += a.x * w.x + a.y * w.y + a.z * w.z + a.w * w.w;
    }
    {
        const float4* hp = (const float4*)&g_h2[(size_t)s * H2DIM];
        float4 a = hp[lane]; float4 w = ow4[ATTFLAT / 4 + lane];
        acc += a.x * w.x + a.y * w.y + a.z * w.z + a.w * w.w;
    }
    float al = X[(size_t)s * XCOLS + lane] * linW[lane];
    if (lane < XCOLS - 32) al += X[(size_t)s * XCOLS + 32 + lane] * linW[32 + lane];
#pragma unroll
    for (int o = 16; o > 0; o >>= 1) {
        acc += __shfl_xor_sync(0xffffffffu, acc, o);
        al  += __shfl_xor_sync(0xffffffffu, al, o);
    }
    if (lane == 0) {
        float lin = fmaxf(al + linb[0], 0.f);
        out[s] = 1.f / (1.f + expf(-(lin + acc)));
    }
}

// ---------------- launcher ----------------
extern "C" void kernel_launch(void* const* d_in, const int* in_sizes, int n_in,
                              void* d_out, int out_size) {
    (void)in_sizes; (void)n_in; (void)out_size;
    const float* X    = (const float*)d_in[0];
    const int*   sidx = (const int*)  d_in[1];
    const float* emb  = (const float*)d_in[2];
    const float* Wq   = (const float*)d_in[3];
    const float* Wk   = (const float*)d_in[4];
    const float* Wv   = (const float*)d_in[5];
    const float* Wr   = (const float*)d_in[6];
    const float* W1   = (const float*)d_in[7];
    const float* b1   = (const float*)d_in[8];
    const float* W2   = (const float*)d_in[9];
    const float* b2   = (const float*)d_in[10];
    const float* outW = (const float*)d_in[11];
    const float* linW = (const float*)d_in[12];
    const float* linb = (const float*)d_in[13];
    float* out = (float*)d_out;

    {
        long total = (long)BATCH * DNNIN_PAD;
        int blocks = (int)((total + 255) / 256);
        gather_kernel<<<blocks, 256>>>(X, sidx, emb);
    }
    for (int l = 0; l < NLAYER; l++) {
        proj_gemm<<<dim3(MROWS / GBM, QKVR_C / GBN), 256>>>(
            Wq + (long)l * EDIM * EDIM, Wk + (long)l * EDIM * EDIM,
            Wv + (long)l * EDIM * EDIM, Wr + (long)l * EDIM * EDIM);
        attn_kernel<<<BATCH / AT_SAMPLES, 128>>>();
    }
    dnn_gemm<<<dim3(BATCH / GBM, H1DIM / GBN), 256>>>(W1, b1);
    h2_gemm<<<BATCH / GBM, 256>>>(W2, b2);
    head_kernel<<<BATCH / 8, 256>>>(X, outW, linW, linb, out);
}

// round 7
// speedup vs baseline: 2.6709x; 1.7718x over previous
#include <cuda_runtime.h>
#include <cuda_bf16.h>
#include <cstdint>
#include <math.h>

// ---------------- problem constants ----------------
#define BATCH     32768
#define NSPARSE   26
#define NDENSE    13
#define VOCAB     10000
#define EDIM      64
#define NHEAD     2
#define DHEAD     32
#define NLAYER    3
#define H1DIM     256
#define H2DIM     128
#define DNNIN     1677
#define KPAD      1728            // 27 * 64
#define XCOLS     39
#define ATTFLAT   (NSPARSE*EDIM)  // 1664
#define QKVR_C    256
#define MROWS     (BATCH*NSPARSE) // 851968
#define STACKW    (ATTFLAT + H2DIM)

// ---------------- scratch (device globals) ----------------
__device__ float          g_att[(size_t)BATCH * ATTFLAT];      // fp32 att (after layer 3 only)
__device__ __nv_bfloat16  g_att_bf[(size_t)MROWS * EDIM];      // bf16 att (GEMM A operand)
__device__ __nv_bfloat16  g_qkvr_bf[(size_t)MROWS * QKVR_C];   // proj output
__device__ __nv_bfloat16  g_dnn_bf[(size_t)BATCH * KPAD];      // dnn input (padded, bf16)
__device__ __nv_bfloat16  g_h1_bf[(size_t)BATCH * H1DIM];
__device__ float          g_h2[(size_t)BATCH * H2DIM];
// prepacked B operands [N][K] bf16
__device__ __nv_bfloat16  g_wqkvr_bf[NLAYER * QKVR_C * EDIM];
__device__ __nv_bfloat16  g_w1_bf[H1DIM * KPAD];
__device__ __nv_bfloat16  g_w2_bf[H2DIM * H1DIM];

// ---------------- mma.sync helpers (sm_80+ path, no 'a'-gated features) ----
__device__ __forceinline__ uint32_t smem_u32(const void* p) {
    uint32_t a;
    asm("{ .reg .u64 t; cvta.to.shared.u64 t, %1; cvt.u32.u64 %0, t; }" : "=r"(a) : "l"(p));
    return a;
}
#define LDSM_X4(d, addr) \
    asm volatile("ldmatrix.sync.aligned.m8n8.x4.shared.b16 {%0,%1,%2,%3}, [%4];" \
        : "=r"((d)[0]), "=r"((d)[1]), "=r"((d)[2]), "=r"((d)[3]) : "r"(addr))

__device__ __forceinline__ void mma_bf16(float* c, const uint32_t* a,
                                         uint32_t b0, uint32_t b1) {
    asm volatile(
        "mma.sync.aligned.m16n8k16.row.col.f32.bf16.bf16.f32 "
        "{%0,%1,%2,%3},{%4,%5,%6,%7},{%8,%9},{%0,%1,%2,%3};"
        : "+f"(c[0]), "+f"(c[1]), "+f"(c[2]), "+f"(c[3])
        : "r"(a[0]), "r"(a[1]), "r"(a[2]), "r"(a[3]), "r"(b0), "r"(b1));
}

// ---------------- weight prep kernels (fp32 -> bf16 [N][K] layout) ----
__global__ void prep_wqkvr(const float* __restrict__ Wq, const float* __restrict__ Wk,
                           const float* __restrict__ Wv, const float* __restrict__ Wr) {
    int idx = blockIdx.x * 256 + threadIdx.x;
    if (idx >= NLAYER * QKVR_C * EDIM) return;
    int l = idx >> 14, rem = idx & 16383;
    int n = rem >> 6, k = rem & 63;
    const float* Ws[4] = {Wq, Wk, Wv, Wr};
    float v = Ws[n >> 6][(l * EDIM + k) * EDIM + (n & 63)];
    g_wqkvr_bf[idx] = __float2bfloat16_rn(v);
}
__global__ void prep_w1(const float* __restrict__ W1) {
    int idx = blockIdx.x * 256 + threadIdx.x;
    if (idx >= H1DIM * KPAD) return;
    int n = idx / KPAD, k = idx % KPAD;
    float v = (k < DNNIN) ? W1[(long)k * H1DIM + n] : 0.f;
    g_w1_bf[idx] = __float2bfloat16_rn(v);
}
__global__ void prep_w2(const float* __restrict__ W2) {
    int idx = blockIdx.x * 256 + threadIdx.x;
    if (idx >= H2DIM * H1DIM) return;
    int n = idx / H1DIM, k = idx % H1DIM;
    g_w2_bf[idx] = __float2bfloat16_rn(W2[(long)k * H2DIM + n]);
}

// ---------------- embedding gather + dnn input (bf16) --------------------
__global__ void gather_kernel(const float* __restrict__ X,
                              const int*   __restrict__ sidx,
                              const float* __restrict__ emb) {
    long idx = (long)blockIdx.x * blockDim.x + threadIdx.x;
    long total = (long)BATCH * KPAD;
    if (idx >= total) return;
    int b = (int)(idx / KPAD);
    int c = (int)(idx % KPAD);
    if (c < NDENSE) {
        g_dnn_bf[idx] = __float2bfloat16_rn(X[(long)b * XCOLS + NSPARSE + c]);
    } else if (c < DNNIN) {
        int j = c - NDENSE;
        int f = j >> 6, e = j & 63;
        int row = sidx[(long)b * NSPARSE + f];
        float v = emb[((long)f * VOCAB + row) * EDIM + e];
        __nv_bfloat16 h = __float2bfloat16_rn(v);
        g_dnn_bf[idx] = h;
        g_att_bf[(long)b * ATTFLAT + j] = h;
    } else {
        g_dnn_bf[idx] = __float2bfloat16_rn(0.f);
    }
}

// ---------------- bf16 mma.sync GEMM ----------------
// C[M, NTFULL] = A[M, KTOT] @ B[NTFULL, KTOT]^T ; CTA tile 128x128, 8 warps.
// smem tiles 128 rows x 128 bytes, SW128 xor-swizzled (conflict-free ldmatrix).
template<int KTOT, int NTFULL, bool RELU, bool BF16OUT>
__global__ __launch_bounds__(256)
void gemm_mma(const __nv_bfloat16* __restrict__ A,
              const __nv_bfloat16* __restrict__ Bop,
              const float* __restrict__ bias,
              void* __restrict__ Cout) {
    __shared__ __align__(1024) unsigned char smA[128 * 128];
    __shared__ __align__(1024) unsigned char smB[128 * 128];
    const int tid = threadIdx.x;
    const int wid = tid >> 5, lane = tid & 31;
    const int wm = wid & 3, wn = wid >> 2;       // 4x2 warp grid -> warp tile 32x64
    const long m0 = (long)blockIdx.x * 128;
    const int n0 = blockIdx.y * 128;

    float acc[2][8][4];
#pragma unroll
    for (int mi = 0; mi < 2; mi++)
#pragma unroll
        for (int ni = 0; ni < 8; ni++)
#pragma unroll
            for (int q = 0; q < 4; q++) acc[mi][ni][q] = 0.f;

    const uint32_t sA = smem_u32(smA), sB = smem_u32(smB);

    // per-lane ldmatrix address components
    const int sel = lane >> 3, rr = lane & 7;
    const int arow0 = wm * 32 + (sel & 1) * 8 + rr;   // + mi*16
    const int ahi = sel >> 1;                          // col-16B-half select
    const int brow0 = wn * 64 + (sel >> 1) * 8 + rr;   // + nip*16
    const int bhi = sel & 1;

    const int NCH = KTOT / 64;
    for (int ch = 0; ch < NCH; ch++) {
        const unsigned char* Ag = (const unsigned char*)A + (m0 * KTOT + (long)ch * 64) * 2;
        const unsigned char* Bg = (const unsigned char*)Bop + (((long)n0 * KTOT) + (long)ch * 64) * 2;
#pragma unroll 2
        for (int u = tid; u < 1024; u += 256) {
            int r = u >> 3, ck = u & 7;
            uint32_t so = (uint32_t)(r * 128 + ((ck ^ (r & 7)) << 4));
            *(uint4*)(smA + so) = *(const uint4*)(Ag + (long)r * (KTOT * 2) + ck * 16);
            *(uint4*)(smB + so) = *(const uint4*)(Bg + (long)r * (KTOT * 2) + ck * 16);
        }
        __syncthreads();
#pragma unroll
        for (int kk = 0; kk < 4; kk++) {
            uint32_t a[2][4];
#pragma unroll
            for (int mi = 0; mi < 2; mi++) {
                int r = arow0 + mi * 16;
                uint32_t addr = sA + r * 128 + ((uint32_t)((2 * kk + ahi) ^ (r & 7)) << 4);
                LDSM_X4(a[mi], addr);
            }
#pragma unroll
            for (int nip = 0; nip < 4; nip++) {
                int r = brow0 + nip * 16;
                uint32_t addr = sB + r * 128 + ((uint32_t)((2 * kk + bhi) ^ (r & 7)) << 4);
                uint32_t b[4];
                LDSM_X4(b, addr);
#pragma unroll
                for (int mi = 0; mi < 2; mi++) {
                    mma_bf16(acc[mi][nip * 2],     a[mi], b[0], b[1]);
                    mma_bf16(acc[mi][nip * 2 + 1], a[mi], b[2], b[3]);
                }
            }
        }
        __syncthreads();
    }

    // epilogue
    const int g = lane >> 2, t = lane & 3;
#pragma unroll
    for (int mi = 0; mi < 2; mi++) {
#pragma unroll
        for (int ni = 0; ni < 8; ni++) {
            int col = n0 + wn * 64 + ni * 8 + 2 * t;
            long r0 = m0 + wm * 32 + mi * 16 + g;
            float c0 = acc[mi][ni][0], c1 = acc[mi][ni][1];
            float c2 = acc[mi][ni][2], c3 = acc[mi][ni][3];
            if (bias != nullptr) {
                float bb0 = bias[col], bb1 = bias[col + 1];
                c0 += bb0; c1 += bb1; c2 += bb0; c3 += bb1;
            }
            if (RELU) {
                c0 = fmaxf(c0, 0.f); c1 = fmaxf(c1, 0.f);
                c2 = fmaxf(c2, 0.f); c3 = fmaxf(c3, 0.f);
            }
            if (BF16OUT) {
                __nv_bfloat16* base = (__nv_bfloat16*)Cout;
                *(__nv_bfloat162*)(base + r0 * NTFULL + col)       = __floats2bfloat162_rn(c0, c1);
                *(__nv_bfloat162*)(base + (r0 + 8) * NTFULL + col) = __floats2bfloat162_rn(c2, c3);
            } else {
                float* base = (float*)Cout;
                *(float2*)(base + r0 * NTFULL + col)       = make_float2(c0, c1);
                *(float2*)(base + (r0 + 8) * NTFULL + col) = make_float2(c2, c3);
            }
        }
    }
}

// ---------------- attention: warp per (sample, head), bf16 in/out --------
#define AT_SAMPLES 2
#define AT_STRIDE  260
__global__ __launch_bounds__(128)
void attn_kernel(int write_f32) {
    __shared__ __align__(16) float s[AT_SAMPLES * NSPARSE * AT_STRIDE];
    __shared__ float p_s[AT_SAMPLES * NHEAD * NSPARSE * 32];
    int tid = threadIdx.x;
    int warp = tid >> 5, lane = tid & 31;
    int ls = warp >> 1;
    int h  = warp & 1;
    long b0 = (long)blockIdx.x * AT_SAMPLES;

    const uint4* src = (const uint4*)(g_qkvr_bf + (size_t)b0 * NSPARSE * QKVR_C);
    for (int i = tid; i < AT_SAMPLES * NSPARSE * (QKVR_C / 8); i += 128) {
        uint4 u = src[i];
        int r = i >> 5;
        int c = (i & 31) * 8;
        float* d = &s[r * AT_STRIDE + c];
        const __nv_bfloat162* hb = (const __nv_bfloat162*)&u;
        float2 f0 = __bfloat1622float2(hb[0]);
        float2 f1 = __bfloat1622float2(hb[1]);
        float2 f2 = __bfloat1622float2(hb[2]);
        float2 f3 = __bfloat1622float2(hb[3]);
        d[0] = f0.x; d[1] = f0.y; d[2] = f1.x; d[3] = f1.y;
        d[4] = f2.x; d[5] = f2.y; d[6] = f3.x; d[7] = f3.y;
    }
    __syncthreads();

    float* st = &s[ls * NSPARSE * AT_STRIDE];

    float kreg[32];
    if (lane < NSPARSE) {
        const float* kp = &st[lane * AT_STRIDE + EDIM + h * DHEAD];
#pragma unroll
        for (int d = 0; d < 32; d += 4) {
            float4 t = *(const float4*)&kp[d];
            kreg[d] = t.x; kreg[d+1] = t.y; kreg[d+2] = t.z; kreg[d+3] = t.w;
        }
    } else {
#pragma unroll
        for (int d = 0; d < 32; d++) kreg[d] = 0.f;
    }

    float sc[NSPARSE];
#pragma unroll
    for (int i = 0; i < NSPARSE; i++) {
        const float* qp = &st[i * AT_STRIDE + h * DHEAD];
        float acc = 0.f;
#pragma unroll
        for (int d = 0; d < 32; d += 4) {
            float4 q4 = *(const float4*)&qp[d];
            acc += q4.x * kreg[d] + q4.y * kreg[d+1]
                 + q4.z * kreg[d+2] + q4.w * kreg[d+3];
        }
        sc[i] = (lane < NSPARSE) ? acc : -INFINITY;
    }

    float* pp = &p_s[(ls * NHEAD + h) * NSPARSE * 32];
#pragma unroll
    for (int i = 0; i < NSPARSE; i++) {
        float m = sc[i];
#pragma unroll
        for (int o = 16; o > 0; o >>= 1) m = fmaxf(m, __shfl_xor_sync(0xffffffffu, m, o));
        float e = expf(sc[i] - m);
        float ssum = e;
#pragma unroll
        for (int o = 16; o > 0; o >>= 1) ssum += __shfl_xor_sync(0xffffffffu, ssum, o);
        pp[i * 32 + lane] = e / ssum;
    }
    __syncwarp();

    float vreg[NSPARSE];
#pragma unroll
    for (int j = 0; j < NSPARSE; j++)
        vreg[j] = st[j * AT_STRIDE + 2 * EDIM + h * DHEAD + lane];

    size_t obase = (size_t)(b0 + ls) * ATTFLAT + h * DHEAD + lane;
#pragma unroll
    for (int i = 0; i < NSPARSE; i++) {
        float acc = st[i * AT_STRIDE + 3 * EDIM + h * DHEAD + lane];
        const float* pr = &pp[i * 32];
#pragma unroll
        for (int j = 0; j < 24; j += 4) {
            float4 p4 = *(const float4*)&pr[j];
            acc += p4.x * vreg[j] + p4.y * vreg[j+1]
                 + p4.z * vreg[j+2] + p4.w * vreg[j+3];
        }
        acc += pr[24] * vreg[24] + pr[25] * vreg[25];
        acc = fmaxf(acc, 0.f);
        g_att_bf[obase + (size_t)i * EDIM] = __float2bfloat16_rn(acc);
        if (write_f32) g_att[obase + (size_t)i * EDIM] = acc;
    }
}

// ---------------- head: per-sample dots + sigmoid ----------------
__global__ __launch_bounds__(256)
void head_kernel(const float* __restrict__ X,
                 const float* __restrict__ outW,
                 const float* __restrict__ linW, const float* __restrict__ linb,
                 float* __restrict__ out) {
    __shared__ __align__(16) float soW[STACKW];
    int tid = threadIdx.x;
    for (int i = tid; i < STACKW; i += 256) soW[i] = outW[i];
    __syncthreads();
    int warp = tid >> 5, lane = tid & 31;
    int s = blockIdx.x * 8 + warp;
    const float4* ap  = (const float4*)&g_att[(size_t)s * ATTFLAT];
    const float4* ow4 = (const float4*)soW;
    float acc = 0.f;
#pragma unroll
    for (int t = 0; t < 13; t++) {
        int i = t * 32 + lane;
        float4 a = ap[i]; float4 w = ow4[i];
        acc += a.x * w.x + a.y * w.y + a.z * w.z + a.w * w.w;
    }
    {
        const float4* hp = (const float4*)&g_h2[(size_t)s * H2DIM];
        float4 a = hp[lane]; float4 w = ow4[ATTFLAT / 4 + lane];
        acc += a.x * w.x + a.y * w.y + a.z * w.z + a.w * w.w;
    }
    float al = X[(size_t)s * XCOLS + lane] * linW[lane];
    if (lane < XCOLS - 32) al += X[(size_t)s * XCOLS + 32 + lane] * linW[32 + lane];
#pragma unroll
    for (int o = 16; o > 0; o >>= 1) {
        acc += __shfl_xor_sync(0xffffffffu, acc, o);
        al  += __shfl_xor_sync(0xffffffffu, al, o);
    }
    if (lane == 0) {
        float lin = fmaxf(al + linb[0], 0.f);
        out[s] = 1.f / (1.f + expf(-(lin + acc)));
    }
}

// ---------------- launcher ----------------
extern "C" void kernel_launch(void* const* d_in, const int* in_sizes, int n_in,
                              void* d_out, int out_size) {
    (void)in_sizes; (void)n_in; (void)out_size;
    const float* X    = (const float*)d_in[0];
    const int*   sidx = (const int*)  d_in[1];
    const float* emb  = (const float*)d_in[2];
    const float* Wq   = (const float*)d_in[3];
    const float* Wk   = (const float*)d_in[4];
    const float* Wv   = (const float*)d_in[5];
    const float* Wr   = (const float*)d_in[6];
    const float* W1   = (const float*)d_in[7];
    const float* b1   = (const float*)d_in[8];
    const float* W2   = (const float*)d_in[9];
    const float* b2   = (const float*)d_in[10];
    const float* outW = (const float*)d_in[11];
    const float* linW = (const float*)d_in[12];
    const float* linb = (const float*)d_in[13];
    float* out = (float*)d_out;

    void *pAttBf, *pQkvr, *pDnn, *pH1, *pH2, *pWqkvr, *pW1b, *pW2b;
    cudaGetSymbolAddress(&pAttBf, g_att_bf);
    cudaGetSymbolAddress(&pQkvr,  g_qkvr_bf);
    cudaGetSymbolAddress(&pDnn,   g_dnn_bf);
    cudaGetSymbolAddress(&pH1,    g_h1_bf);
    cudaGetSymbolAddress(&pH2,    g_h2);
    cudaGetSymbolAddress(&pWqkvr, g_wqkvr_bf);
    cudaGetSymbolAddress(&pW1b,   g_w1_bf);
    cudaGetSymbolAddress(&pW2b,   g_w2_bf);

    prep_wqkvr<<<(NLAYER * QKVR_C * EDIM + 255) / 256, 256>>>(Wq, Wk, Wv, Wr);
    prep_w1<<<(H1DIM * KPAD + 255) / 256, 256>>>(W1);
    prep_w2<<<(H2DIM * H1DIM + 255) / 256, 256>>>(W2);
    {
        long total = (long)BATCH * KPAD;
        gather_kernel<<<(int)((total + 255) / 256), 256>>>(X, sidx, emb);
    }

    for (int l = 0; l < NLAYER; l++) {
        gemm_mma<EDIM, QKVR_C, false, true><<<dim3(MROWS / 128, QKVR_C / 128), 256>>>(
            (const __nv_bfloat16*)pAttBf,
            (const __nv_bfloat16*)pWqkvr + (size_t)l * QKVR_C * EDIM,
            nullptr, pQkvr);
        attn_kernel<<<BATCH / AT_SAMPLES, 128>>>(l == NLAYER - 1 ? 1 : 0);
    }
    gemm_mma<KPAD, H1DIM, true, true><<<dim3(BATCH / 128, H1DIM / 128), 256>>>(
        (const __nv_bfloat16*)pDnn, (const __nv_bfloat16*)pW1b, b1, pH1);
    gemm_mma<H1DIM, H2DIM, true, false><<<dim3(BATCH / 128, 1), 256>>>(
        (const __nv_bfloat16*)pH1, (const __nv_bfloat16*)pW2b, b2, pH2);
    head_kernel<<<BATCH / 8, 256>>>(X, outW, linW, linb, out);
}